// round 6
// baseline (speedup 1.0000x reference)
#include <cuda_runtime.h>
#include <math.h>

#define BB 4
#define SEQ 577
#define DIMM 512
#define NH 8
#define NAA 4
#define MROWS (BB*SEQ)          /* 2308 */
#define QKVN (3*DIMM)           /* 1536 */
#define NN2 (SEQ*SEQ)           /* 332929 */
#define DOTSE (BB*NH*NN2)       /* 10653728 */
#define NROWS (BB*NH*SEQ)       /* 18464 */
#define RPB (NH*SEQ)            /* 4616 rows per batch */
#define SCALE_F 0.125f

// ---------------- scratch (static device globals; no allocation) ----------------
__device__ float g_qkv0[MROWS*QKVN];
__device__ float g_qkv1[MROWS*QKVN];
__device__ float g_dots0[DOTSE];
__device__ float g_dots1[DOTSE];
__device__ float g_ao0[MROWS*DIMM];
__device__ float g_ao1[MROWS*DIMM];
__device__ float g_rmax[2*NROWS];
__device__ float g_rsum[2*NROWS];
__device__ float g_tacc[NROWS];

// ---------------- tf32 helpers ----------------
__device__ __forceinline__ unsigned f2tf(float f){
    unsigned u; asm("cvt.rna.tf32.f32 %0, %1;" : "=r"(u) : "f"(f)); return u;
}
__device__ __forceinline__ void st4tf(unsigned* p, float4 v){
    p[0]=f2tf(v.x); p[1]=f2tf(v.y); p[2]=f2tf(v.z); p[3]=f2tf(v.w);
}
__device__ __forceinline__ void mma8(float* c, unsigned a0, unsigned a1, unsigned a2, unsigned a3,
                                     unsigned b0, unsigned b1){
    asm("mma.sync.aligned.m16n8k8.row.col.f32.tf32.tf32.f32 "
        "{%0,%1,%2,%3},{%4,%5,%6,%7},{%8,%9},{%0,%1,%2,%3};"
        : "+f"(c[0]),"+f"(c[1]),"+f"(c[2]),"+f"(c[3])
        : "r"(a0),"r"(a1),"r"(a2),"r"(a3),"r"(b0),"r"(b1));
}

// ---------------- tf32 GEMM, 2-stage pipelined: C = A[M,K] @ W[K,N] + bias ----------------
// BM=128, BN=128, BK=16, 256 threads, 8 warps as 2x4, warp tile 64x32
__device__ __forceinline__ void gemm_tf32_body(const float* __restrict__ A,
                                               const float* __restrict__ W,
                                               const float* __restrict__ bias,
                                               float* __restrict__ C,
                                               int M, int Nn, int K){
    __shared__ unsigned As[2][128][20];
    __shared__ unsigned Ws[2][16][136];
    const int tid = threadIdx.x;
    const int lane = tid & 31, wrp = tid >> 5;
    const int wm = wrp >> 2, wn = wrp & 3;
    const int m0 = blockIdx.y * 128;
    const int n0 = blockIdx.x * 128;
    const int lr = lane >> 2, lc = lane & 3;

    float acc[4][4][4];
#pragma unroll
    for (int i=0;i<4;i++)
#pragma unroll
        for (int j=0;j<4;j++)
#pragma unroll
            for (int e=0;e<4;e++) acc[i][j][e]=0.f;

    float4 aR[2], wR[2];
    auto LOADG = [&](int k0){
#pragma unroll
        for (int s2=0;s2<2;s2++){
            int idx = tid + s2*256;
            int r = idx >> 2, c = (idx & 3) * 4;
            int gr = m0 + r;
            aR[s2] = (gr < M) ? *reinterpret_cast<const float4*>(&A[(size_t)gr*K + k0 + c])
                              : make_float4(0.f,0.f,0.f,0.f);
            int r2 = idx >> 5, c2 = (idx & 31) * 4;
            wR[s2] = *reinterpret_cast<const float4*>(&W[(size_t)(k0+r2)*Nn + n0 + c2]);
        }
    };
    auto STORES = [&](int st){
#pragma unroll
        for (int s2=0;s2<2;s2++){
            int idx = tid + s2*256;
            int r = idx >> 2, c = (idx & 3) * 4;
            st4tf(&As[st][r][c], aR[s2]);
            int r2 = idx >> 5, c2 = (idx & 31) * 4;
            st4tf(&Ws[st][r2][c2], wR[s2]);
        }
    };

    const int NIT = K/16;
    LOADG(0); STORES(0);
    __syncthreads();
    for (int it=0; it<NIT; it++){
        int st = it & 1;
        bool nxt = (it+1 < NIT);
        if (nxt) LOADG((it+1)*16);
#pragma unroll
        for (int kk=0;kk<16;kk+=8){
            unsigned a[4][4], b[4][2];
#pragma unroll
            for (int mt=0;mt<4;mt++){
                int row = wm*64 + mt*16 + lr;
                a[mt][0]=As[st][row  ][kk+lc];   a[mt][1]=As[st][row+8][kk+lc];
                a[mt][2]=As[st][row  ][kk+lc+4]; a[mt][3]=As[st][row+8][kk+lc+4];
            }
#pragma unroll
            for (int nt=0;nt<4;nt++){
                int col = wn*32 + nt*8 + lr;
                b[nt][0]=Ws[st][kk+lc][col]; b[nt][1]=Ws[st][kk+lc+4][col];
            }
#pragma unroll
            for (int mt=0;mt<4;mt++)
#pragma unroll
                for (int nt=0;nt<4;nt++)
                    mma8(acc[mt][nt], a[mt][0],a[mt][1],a[mt][2],a[mt][3], b[nt][0],b[nt][1]);
        }
        if (nxt) STORES(st^1);
        __syncthreads();
    }
#pragma unroll
    for (int mt=0;mt<4;mt++){
        int r0 = m0 + wm*64 + mt*16 + lr;
#pragma unroll
        for (int nt=0;nt<4;nt++){
            int c0 = n0 + wn*32 + nt*8 + lc*2;
            float b0 = bias[c0], b1 = bias[c0+1];
            if (r0 < M){
                float2 o = make_float2(acc[mt][nt][0]+b0, acc[mt][nt][1]+b1);
                *reinterpret_cast<float2*>(&C[(size_t)r0*Nn + c0]) = o;
            }
            if (r0+8 < M){
                float2 o = make_float2(acc[mt][nt][2]+b0, acc[mt][nt][3]+b1);
                *reinterpret_cast<float2*>(&C[(size_t)(r0+8)*Nn + c0]) = o;
            }
        }
    }
}

__global__ void __launch_bounds__(256) gemm_qkv_kernel(
        const float* __restrict__ x, const float* __restrict__ l,
        const float* __restrict__ wqkv, const float* __restrict__ bqkv,
        const float* __restrict__ wqkv1, const float* __restrict__ bqkv1){
    int s = blockIdx.z;
    gemm_tf32_body(s ? l : x, s ? wqkv1 : wqkv, s ? bqkv1 : bqkv,
                   s ? g_qkv1 : g_qkv0, MROWS, QKVN, DIMM);
}

__global__ void __launch_bounds__(256) gemm_mlp_kernel(
        const float* __restrict__ w_mlp, const float* __restrict__ b_mlp,
        const float* __restrict__ w_mlp1, const float* __restrict__ b_mlp1,
        float* __restrict__ out){
    int s = blockIdx.z;
    gemm_tf32_body(s ? g_ao1 : g_ao0, s ? w_mlp1 : w_mlp, s ? b_mlp1 : b_mlp,
                   out + (size_t)s*MROWS*DIMM, MROWS, DIMM, DIMM);
}

// ---------------- fused dots + sup + online row softmax stats + KL row terms ----------------
// one block per (bh, 64-row strip); loops over 5 j-tiles of 128 cols.
// running per-row (m,s) with rescale combine; t = sum e^{d1-m1}(d1-d0) likewise.
__global__ void __launch_bounds__(256) dots_fused_kernel(
        const float* __restrict__ c1w, const float* __restrict__ c1b,
        const float* __restrict__ bn_g, const float* __restrict__ bn_b,
        const float* __restrict__ bn_m, const float* __restrict__ bn_v,
        const float* __restrict__ c2w, const float* __restrict__ c2b){
    __shared__ unsigned Qs[2][64][20];
    __shared__ unsigned Ks[2][128][20];
    __shared__ float redM[2][64][4];
    __shared__ float redS[2][64][4];
    __shared__ float redT[64][4];
    __shared__ float runM0[64], runS0[64], runM1[64], runS1[64], runT[64];

    const int tid = threadIdx.x;
    const int lane = tid & 31, wrp = tid >> 5;
    const int wm = wrp >> 2, wn = wrp & 3;
    const int lr = lane >> 2, lc = lane & 3;
    const int bh = blockIdx.y;
    const int b = bh >> 3, h = bh & 7;
    const int i0 = blockIdx.x * 64;

    const float* qp0 = g_qkv0 + (size_t)b*SEQ*QKVN + h*64;
    const float* qp1 = g_qkv1 + (size_t)b*SEQ*QKVN + h*64;
    const float* kp0 = qp0 + DIMM;
    const float* kp1 = qp1 + DIMM;
    const size_t rbase = (size_t)bh*SEQ;

    if (tid < 64){
        runM0[tid]=-INFINITY; runS0[tid]=0.f;
        runM1[tid]=-INFINITY; runS1[tid]=0.f; runT[tid]=0.f;
    }

    // per-head fused conv->BN->leaky->conv coefficients
    float Ao[NAA], Bo[NAA], Co[NAA], Wo[NAA];
#pragma unroll
    for (int o=0;o<NAA;o++){
        int idx = h*NAA + o;
        float inv = rsqrtf(bn_v[idx] + 1e-5f) * bn_g[idx];
        Ao[o] = c1w[idx*2]   * inv;
        Bo[o] = c1w[idx*2+1] * inv;
        Co[o] = (c1b[idx] - bn_m[idx]) * inv + bn_b[idx];
        Wo[o] = c2w[idx];
    }
    const float c2bh = c2b[h];
    __syncthreads();

    for (int j0=0; j0<SEQ; j0+=128){
        float acc[2][2][4][4];
#pragma unroll
        for (int s=0;s<2;s++)
#pragma unroll
            for (int mt=0;mt<2;mt++)
#pragma unroll
                for (int nt=0;nt<4;nt++)
#pragma unroll
                    for (int e=0;e<4;e++) acc[s][mt][nt][e]=0.f;

        for (int c0=0;c0<64;c0+=16){
            {   // Q tiles: 64x16 per stream
                int r = tid >> 2, c = (tid & 3) * 4;
                int gi = i0 + r;
                float4 v0 = make_float4(0,0,0,0), v1 = v0;
                if (gi < SEQ){
                    v0 = *reinterpret_cast<const float4*>(&qp0[(size_t)gi*QKVN + c0 + c]);
                    v1 = *reinterpret_cast<const float4*>(&qp1[(size_t)gi*QKVN + c0 + c]);
                }
                st4tf(&Qs[0][r][c], v0);
                st4tf(&Qs[1][r][c], v1);
            }
#pragma unroll
            for (int t=0;t<2;t++){ // K tiles: 128x16 per stream
                int idx = tid + t*256;
                int r = idx >> 2, c = (idx & 3) * 4;
                int gj = j0 + r;
                float4 v0 = make_float4(0,0,0,0), v1 = v0;
                if (gj < SEQ){
                    v0 = *reinterpret_cast<const float4*>(&kp0[(size_t)gj*QKVN + c0 + c]);
                    v1 = *reinterpret_cast<const float4*>(&kp1[(size_t)gj*QKVN + c0 + c]);
                }
                st4tf(&Ks[0][r][c], v0);
                st4tf(&Ks[1][r][c], v1);
            }
            __syncthreads();
#pragma unroll
            for (int kk=0;kk<16;kk+=8){
                unsigned a[2][2][4], bb[2][4][2];
#pragma unroll
                for (int s=0;s<2;s++){
#pragma unroll
                    for (int mt=0;mt<2;mt++){
                        int row = wm*32 + mt*16 + lr;
                        a[s][mt][0]=Qs[s][row  ][kk+lc];   a[s][mt][1]=Qs[s][row+8][kk+lc];
                        a[s][mt][2]=Qs[s][row  ][kk+lc+4]; a[s][mt][3]=Qs[s][row+8][kk+lc+4];
                    }
#pragma unroll
                    for (int nt=0;nt<4;nt++){
                        int col = wn*32 + nt*8 + lr;
                        bb[s][nt][0]=Ks[s][col][kk+lc]; bb[s][nt][1]=Ks[s][col][kk+lc+4];
                    }
                }
#pragma unroll
                for (int s=0;s<2;s++)
#pragma unroll
                    for (int mt=0;mt<2;mt++)
#pragma unroll
                        for (int nt=0;nt<4;nt++)
                            mma8(acc[s][mt][nt], a[s][mt][0],a[s][mt][1],a[s][mt][2],a[s][mt][3],
                                 bb[s][nt][0],bb[s][nt][1]);
            }
            __syncthreads();
        }

        // ---- epilogue: transform + write + tile stats + running combine ----
        float mloc[2][4];
#pragma unroll
        for (int s=0;s<2;s++)
#pragma unroll
            for (int q=0;q<4;q++) mloc[s][q] = -INFINITY;

#pragma unroll
        for (int mt=0;mt<2;mt++){
#pragma unroll
            for (int half=0;half<2;half++){
                const int q = mt*2+half;
                const int gi = i0 + wm*32 + mt*16 + half*8 + lr;
#pragma unroll
                for (int nt=0;nt<4;nt++){
#pragma unroll
                    for (int e2=0;e2<2;e2++){
                        const int idx = half*2+e2;
                        const int gj = j0 + wn*32 + nt*8 + lc*2 + e2;
                        float d  = acc[0][mt][nt][idx]*SCALE_F;
                        float d1 = acc[1][mt][nt][idx]*SCALE_F;
                        float sup = c2bh;
#pragma unroll
                        for (int o=0;o<NAA;o++){
                            float t = fmaf(Ao[o], d, fmaf(Bo[o], d1, Co[o]));
                            t = (t > 0.f) ? t : 0.01f*t;
                            sup = fmaf(t, Wo[o], sup);
                        }
                        float fd = d + sup, fd1 = d1 + sup;
                        acc[0][mt][nt][idx] = fd;
                        acc[1][mt][nt][idx] = fd1;
                        if (gi < SEQ && gj < SEQ){
                            size_t off = (rbase + gi)*SEQ + gj;
                            g_dots0[off] = fd;
                            g_dots1[off] = fd1;
                            mloc[0][q] = fmaxf(mloc[0][q], fd);
                            mloc[1][q] = fmaxf(mloc[1][q], fd1);
                        }
                    }
                }
            }
        }
        // reduce max across lc-quad
#pragma unroll
        for (int s=0;s<2;s++)
#pragma unroll
            for (int q=0;q<4;q++){
                float m = mloc[s][q];
                m = fmaxf(m, __shfl_xor_sync(0xffffffffu, m, 1));
                m = fmaxf(m, __shfl_xor_sync(0xffffffffu, m, 2));
                mloc[s][q] = m;
            }
        if (lc==0){
#pragma unroll
            for (int s=0;s<2;s++)
#pragma unroll
                for (int q=0;q<4;q++){
                    int row_l = wm*32 + (q>>1)*16 + (q&1)*8 + lr;
                    redM[s][row_l][wn] = mloc[s][q];
                }
        }
        __syncthreads();
        float mt_[2][4];
#pragma unroll
        for (int s=0;s<2;s++)
#pragma unroll
            for (int q=0;q<4;q++){
                int row_l = wm*32 + (q>>1)*16 + (q&1)*8 + lr;
                float m = fmaxf(fmaxf(redM[s][row_l][0], redM[s][row_l][1]),
                                fmaxf(redM[s][row_l][2], redM[s][row_l][3]));
                mt_[s][q] = m;
            }
        float sloc[2][4], tloc[4];
#pragma unroll
        for (int q=0;q<4;q++){ sloc[0][q]=0.f; sloc[1][q]=0.f; tloc[q]=0.f; }
#pragma unroll
        for (int mt=0;mt<2;mt++){
#pragma unroll
            for (int half=0;half<2;half++){
                const int q = mt*2+half;
                const int gi = i0 + wm*32 + mt*16 + half*8 + lr;
#pragma unroll
                for (int nt=0;nt<4;nt++){
#pragma unroll
                    for (int e2=0;e2<2;e2++){
                        const int idx = half*2+e2;
                        const int gj = j0 + wn*32 + nt*8 + lc*2 + e2;
                        if (gi < SEQ && gj < SEQ){
                            float fd = acc[0][mt][nt][idx], fd1 = acc[1][mt][nt][idx];
                            float e0 = __expf(fd  - mt_[0][q]); sloc[0][q] += e0;
                            float e1 = __expf(fd1 - mt_[1][q]); sloc[1][q] += e1;
                            tloc[q] = fmaf(e1, fd1 - fd, tloc[q]);
                        }
                    }
                }
            }
        }
#pragma unroll
        for (int q=0;q<4;q++){
#pragma unroll
            for (int s=0;s<2;s++){
                float v = sloc[s][q];
                v += __shfl_xor_sync(0xffffffffu, v, 1);
                v += __shfl_xor_sync(0xffffffffu, v, 2);
                sloc[s][q] = v;
            }
            float v = tloc[q];
            v += __shfl_xor_sync(0xffffffffu, v, 1);
            v += __shfl_xor_sync(0xffffffffu, v, 2);
            tloc[q] = v;
        }
        if (lc==0){
#pragma unroll
            for (int q=0;q<4;q++){
                int row_l = wm*32 + (q>>1)*16 + (q&1)*8 + lr;
                redS[0][row_l][wn] = sloc[0][q];
                redS[1][row_l][wn] = sloc[1][q];
                redT[row_l][wn]    = tloc[q];
            }
        }
        __syncthreads();
        if (tid < 64){
            const int row_l = tid;
            float m0t = fmaxf(fmaxf(redM[0][row_l][0], redM[0][row_l][1]),
                              fmaxf(redM[0][row_l][2], redM[0][row_l][3]));
            float m1t = fmaxf(fmaxf(redM[1][row_l][0], redM[1][row_l][1]),
                              fmaxf(redM[1][row_l][2], redM[1][row_l][3]));
            float s0t = redS[0][row_l][0]+redS[0][row_l][1]+redS[0][row_l][2]+redS[0][row_l][3];
            float s1t = redS[1][row_l][0]+redS[1][row_l][1]+redS[1][row_l][2]+redS[1][row_l][3];
            float tt  = redT[row_l][0]+redT[row_l][1]+redT[row_l][2]+redT[row_l][3];
            if (m0t != -INFINITY){
                float mn = fmaxf(runM0[row_l], m0t);
                runS0[row_l] = runS0[row_l]*__expf(runM0[row_l]-mn) + s0t*__expf(m0t-mn);
                runM0[row_l] = mn;
            }
            if (m1t != -INFINITY){
                float mn = fmaxf(runM1[row_l], m1t);
                float eA = __expf(runM1[row_l]-mn), eB = __expf(m1t-mn);
                runS1[row_l] = runS1[row_l]*eA + s1t*eB;
                runT[row_l]  = runT[row_l]*eA  + tt*eB;
                runM1[row_l] = mn;
            }
        }
        __syncthreads();
    }

    if (tid < 64){
        int gi = i0 + tid;
        if (gi < SEQ){
            int row = bh*SEQ + gi;
            g_rmax[row]        = runM0[tid];
            g_rsum[row]        = runS0[tid];
            g_rmax[NROWS+row]  = runM1[tid];
            g_rsum[NROWS+row]  = runS1[tid];
            g_tacc[row]        = runT[tid];
        }
    }
}

// ---------------- KL loss from per-row stats (associative rescale combine) ----------------
__global__ void __launch_bounds__(256) loss_kernel(float* __restrict__ out_loss){
    __shared__ float sM0[256], sS0[256], sM1[256], sS1[256], sT[256];
    const int t = threadIdx.x;
    float total = 0.f;
    for (int b=0;b<BB;b++){
        float M0=-INFINITY, S0=0.f, M1=-INFINITY, S1=0.f, T=0.f;
        for (int r=t; r<RPB; r+=256){
            int row = b*RPB + r;
            float m0 = g_rmax[row], s0 = g_rsum[row];
            float mn0 = fmaxf(M0, m0);
            S0 = S0*__expf(M0-mn0) + s0*__expf(m0-mn0);
            M0 = mn0;
            float m1 = g_rmax[NROWS+row], s1 = g_rsum[NROWS+row], tt = g_tacc[row];
            float mn1 = fmaxf(M1, m1);
            float eA = __expf(M1-mn1), eB = __expf(m1-mn1);
            S1 = S1*eA + s1*eB;
            T  = T*eA  + tt*eB;
            M1 = mn1;
        }
        sM0[t]=M0; sS0[t]=S0; sM1[t]=M1; sS1[t]=S1; sT[t]=T;
        __syncthreads();
        for (int off=128; off; off>>=1){
            if (t < off){
                float m0a=sM0[t], m0b=sM0[t+off];
                float mn0=fmaxf(m0a,m0b);
                sS0[t] = sS0[t]*__expf(m0a-mn0) + sS0[t+off]*__expf(m0b-mn0);
                sM0[t] = mn0;
                float m1a=sM1[t], m1b=sM1[t+off];
                float mn1=fmaxf(m1a,m1b);
                float eA=__expf(m1a-mn1), eB=__expf(m1b-mn1);
                sS1[t] = sS1[t]*eA + sS1[t+off]*eB;
                sT[t]  = sT[t]*eA  + sT[t+off]*eB;
                sM1[t] = mn1;
            }
            __syncthreads();
        }
        if (t==0){
            total += sT[0]/sS1[0] + (sM0[0]+logf(sS0[0])) - (sM1[0]+logf(sS1[0]));
        }
        __syncthreads();
    }
    if (t==0) *out_loss = total * (1.0f/BB);
}

// ---------------- attn @ V, tf32 MMA, fused softmax normalization ----------------
__global__ void __launch_bounds__(256) attnv_kernel(){
    __shared__ unsigned Es[64][36];
    __shared__ unsigned Vs[32][72];
    __shared__ float rm[64], rs[64];
    const int tid = threadIdx.x;
    const int lane = tid & 31, wrp = tid >> 5;
    const int wm = wrp >> 2, wn = wrp & 3;
    const int lr = lane >> 2, lc = lane & 3;
    const int z = blockIdx.z;
    const int s = z >> 5, bh = z & 31;
    const int b = bh >> 3, h = bh & 7;
    const int i0 = blockIdx.y * 64;
    const float* dots = (s ? g_dots1 : g_dots0) + (size_t)bh*NN2;
    const float* vptr = (s ? g_qkv1 : g_qkv0) + (size_t)b*SEQ*QKVN + 2*DIMM + h*64;
    float* ao = (s ? g_ao1 : g_ao0) + (size_t)b*SEQ*DIMM + h*64;

    if (tid < 64){
        int gi = i0 + tid;
        int ri = s*NROWS + bh*SEQ + gi;
        rm[tid] = (gi<SEQ) ? g_rmax[ri] : 0.f;
        rs[tid] = (gi<SEQ) ? g_rsum[ri] : 1.f;
    }
    __syncthreads();

    float acc[2][2][4];
#pragma unroll
    for (int mt=0;mt<2;mt++)
#pragma unroll
        for (int nt=0;nt<2;nt++)
#pragma unroll
            for (int e=0;e<4;e++) acc[mt][nt][e]=0.f;

    for (int j0=0; j0<SEQ; j0+=32){
#pragma unroll
        for (int t=0;t<8;t++){   // Es: 64x32 exps, 8/thread
            int idx = tid + t*256;
            int i = idx >> 5, j = idx & 31;
            int gi = i0+i, gj = j0+j;
            float w = 0.f;
            if (gi < SEQ && gj < SEQ) w = __expf(dots[(size_t)gi*SEQ+gj] - rm[i]);
            Es[i][j] = f2tf(w);
        }
#pragma unroll
        for (int t=0;t<2;t++){   // Vs: 32x64, 2 float4/thread
            int idx = tid + t*256;
            int j = idx >> 4, c = (idx & 15)*4;
            int gj = j0 + j;
            float4 v = make_float4(0,0,0,0);
            if (gj < SEQ) v = *reinterpret_cast<const float4*>(&vptr[(size_t)gj*QKVN + c]);
            st4tf(&Vs[j][c], v);
        }
        __syncthreads();
#pragma unroll
        for (int kk=0;kk<32;kk+=8){
            unsigned a[2][4], bf[2][2];
#pragma unroll
            for (int mt=0;mt<2;mt++){
                int row = wm*32 + mt*16 + lr;
                a[mt][0]=Es[row  ][kk+lc];   a[mt][1]=Es[row+8][kk+lc];
                a[mt][2]=Es[row  ][kk+lc+4]; a[mt][3]=Es[row+8][kk+lc+4];
            }
#pragma unroll
            for (int nt=0;nt<2;nt++){
                int col = wn*16 + nt*8 + lr;
                bf[nt][0]=Vs[kk+lc][col]; bf[nt][1]=Vs[kk+lc+4][col];
            }
#pragma unroll
            for (int mt=0;mt<2;mt++)
#pragma unroll
                for (int nt=0;nt<2;nt++)
                    mma8(acc[mt][nt], a[mt][0],a[mt][1],a[mt][2],a[mt][3], bf[nt][0],bf[nt][1]);
        }
        __syncthreads();
    }
#pragma unroll
    for (int mt=0;mt<2;mt++){
        int lrow = wm*32 + mt*16 + lr;
        int r0 = i0 + lrow;
#pragma unroll
        for (int nt=0;nt<2;nt++){
            int c0 = wn*16 + nt*8 + lc*2;
            if (r0 < SEQ){
                float inv = 1.f / rs[lrow];
                float2 o = make_float2(acc[mt][nt][0]*inv, acc[mt][nt][1]*inv);
                *reinterpret_cast<float2*>(&ao[(size_t)r0*DIMM + c0]) = o;
            }
            if (r0+8 < SEQ){
                float inv = 1.f / rs[lrow+8];
                float2 o = make_float2(acc[mt][nt][2]*inv, acc[mt][nt][3]*inv);
                *reinterpret_cast<float2*>(&ao[(size_t)(r0+8)*DIMM + c0]) = o;
            }
        }
    }
}

// ---------------- host launcher ----------------
extern "C" void kernel_launch(void* const* d_in, const int* in_sizes, int n_in,
                              void* d_out, int out_size){
    (void)in_sizes; (void)n_in; (void)out_size;
    const float* x     = (const float*)d_in[0];
    const float* l     = (const float*)d_in[1];
    /* d_in[2] = mask: unused by the module */
    const float* wqkv  = (const float*)d_in[3];
    const float* bqkv  = (const float*)d_in[4];
    const float* wqkv1 = (const float*)d_in[5];
    const float* bqkv1 = (const float*)d_in[6];
    const float* w_mlp  = (const float*)d_in[7];
    const float* b_mlp  = (const float*)d_in[8];
    const float* w_mlp1 = (const float*)d_in[9];
    const float* b_mlp1 = (const float*)d_in[10];
    const float* c1w  = (const float*)d_in[11];
    const float* c1b  = (const float*)d_in[12];
    const float* bn_g = (const float*)d_in[13];
    const float* bn_b = (const float*)d_in[14];
    const float* bn_m = (const float*)d_in[15];
    const float* bn_v = (const float*)d_in[16];
    const float* c2w  = (const float*)d_in[17];
    const float* c2b  = (const float*)d_in[18];
    float* out = (float*)d_out;

    gemm_qkv_kernel<<<dim3(QKVN/128, (MROWS+127)/128, 2), 256>>>(x, l, wqkv, bqkv, wqkv1, bqkv1);
    dots_fused_kernel<<<dim3(10, BB*NH), 256>>>(c1w, c1b, bn_g, bn_b, bn_m, bn_v, c2w, c2b);
    loss_kernel<<<1, 256>>>(out + 2*(size_t)MROWS*DIMM);
    attnv_kernel<<<dim3(1, 10, 64), 256>>>();
    gemm_mlp_kernel<<<dim3(DIMM/128, (MROWS+127)/128, 2), 256>>>(w_mlp, b_mlp, w_mlp1, b_mlp1, out);
}

// round 7
// speedup vs baseline: 1.2685x; 1.2685x over previous
#include <cuda_runtime.h>
#include <math.h>

#define BB 4
#define SEQ 577
#define DIMM 512
#define NH 8
#define NAA 4
#define MROWS (BB*SEQ)          /* 2308 */
#define QKVN (3*DIMM)           /* 1536 */
#define NN2 (SEQ*SEQ)           /* 332929 */
#define DOTSE (BB*NH*NN2)       /* 10653728 */
#define NROWS (BB*NH*SEQ)       /* 18464 */
#define SCALE_F 0.125f
#define PPB 577                 /* partial blocks per batch in rowkl */

// ---------------- scratch (static device globals; no allocation) ----------------
__device__ float g_qkv0[MROWS*QKVN];
__device__ float g_qkv1[MROWS*QKVN];
__device__ float g_dots0[DOTSE];
__device__ float g_dots1[DOTSE];
__device__ float g_ao0[MROWS*DIMM];   // attnv partial, j-half 0
__device__ float g_ao1[MROWS*DIMM];
__device__ float g_ap0[MROWS*DIMM];   // attnv partial, j-half 1
__device__ float g_ap1[MROWS*DIMM];
__device__ float g_rmax[2*NROWS];
__device__ float g_rsum[2*NROWS];
__device__ float g_bmax[2*BB];
__device__ float g_part[BB*PPB*3];

__device__ __forceinline__ void atomicMaxFloat(float* addr, float val){
    int* ai = (int*)addr;
    int old = *ai;
    while (__int_as_float(old) < val){
        int assumed = old;
        old = atomicCAS(ai, assumed, __float_as_int(val));
        if (old == assumed) break;
    }
}

__global__ void init_kernel(){
    int t = threadIdx.x;
    if (t < 2*BB) g_bmax[t] = -INFINITY;
}

// ---------------- tf32 helpers ----------------
__device__ __forceinline__ unsigned f2tf(float f){
    unsigned u; asm("cvt.rna.tf32.f32 %0, %1;" : "=r"(u) : "f"(f)); return u;
}
__device__ __forceinline__ void st4tf(unsigned* p, float4 v){
    p[0]=f2tf(v.x); p[1]=f2tf(v.y); p[2]=f2tf(v.z); p[3]=f2tf(v.w);
}
__device__ __forceinline__ void mma8(float* c, unsigned a0, unsigned a1, unsigned a2, unsigned a3,
                                     unsigned b0, unsigned b1){
    asm("mma.sync.aligned.m16n8k8.row.col.f32.tf32.tf32.f32 "
        "{%0,%1,%2,%3},{%4,%5,%6,%7},{%8,%9},{%0,%1,%2,%3};"
        : "+f"(c[0]),"+f"(c[1]),"+f"(c[2]),"+f"(c[3])
        : "r"(a0),"r"(a1),"r"(a2),"r"(a3),"r"(b0),"r"(b1));
}

// ---------------- tf32 GEMM, 2-stage pipelined: C = (A [+A2]) @ W + bias ----------------
// BM=128, BN=128, BK=16, 256 threads, 8 warps as 2x4, warp tile 64x32
template<bool DUAL>
__device__ __forceinline__ void gemm_tf32_body(const float* __restrict__ A,
                                               const float* __restrict__ A2,
                                               const float* __restrict__ W,
                                               const float* __restrict__ bias,
                                               float* __restrict__ C,
                                               int M, int Nn, int K){
    __shared__ unsigned As[2][128][20];
    __shared__ unsigned Ws[2][16][136];
    const int tid = threadIdx.x;
    const int lane = tid & 31, wrp = tid >> 5;
    const int wm = wrp >> 2, wn = wrp & 3;
    const int m0 = blockIdx.y * 128;
    const int n0 = blockIdx.x * 128;
    const int lr = lane >> 2, lc = lane & 3;

    float acc[4][4][4];
#pragma unroll
    for (int i=0;i<4;i++)
#pragma unroll
        for (int j=0;j<4;j++)
#pragma unroll
            for (int e=0;e<4;e++) acc[i][j][e]=0.f;

    float4 aR[2], wR[2];
    auto LOADG = [&](int k0){
#pragma unroll
        for (int s2=0;s2<2;s2++){
            int idx = tid + s2*256;
            int r = idx >> 2, c = (idx & 3) * 4;
            int gr = m0 + r;
            float4 v = make_float4(0.f,0.f,0.f,0.f);
            if (gr < M){
                v = *reinterpret_cast<const float4*>(&A[(size_t)gr*K + k0 + c]);
                if (DUAL){
                    float4 v2 = *reinterpret_cast<const float4*>(&A2[(size_t)gr*K + k0 + c]);
                    v.x+=v2.x; v.y+=v2.y; v.z+=v2.z; v.w+=v2.w;
                }
            }
            aR[s2] = v;
            int r2 = idx >> 5, c2 = (idx & 31) * 4;
            wR[s2] = *reinterpret_cast<const float4*>(&W[(size_t)(k0+r2)*Nn + n0 + c2]);
        }
    };
    auto STORES = [&](int st){
#pragma unroll
        for (int s2=0;s2<2;s2++){
            int idx = tid + s2*256;
            int r = idx >> 2, c = (idx & 3) * 4;
            st4tf(&As[st][r][c], aR[s2]);
            int r2 = idx >> 5, c2 = (idx & 31) * 4;
            st4tf(&Ws[st][r2][c2], wR[s2]);
        }
    };

    const int NIT = K/16;
    LOADG(0); STORES(0);
    __syncthreads();
    for (int it=0; it<NIT; it++){
        int st = it & 1;
        bool nxt = (it+1 < NIT);
        if (nxt) LOADG((it+1)*16);
#pragma unroll
        for (int kk=0;kk<16;kk+=8){
            unsigned a[4][4], b[4][2];
#pragma unroll
            for (int mt=0;mt<4;mt++){
                int row = wm*64 + mt*16 + lr;
                a[mt][0]=As[st][row  ][kk+lc];   a[mt][1]=As[st][row+8][kk+lc];
                a[mt][2]=As[st][row  ][kk+lc+4]; a[mt][3]=As[st][row+8][kk+lc+4];
            }
#pragma unroll
            for (int nt=0;nt<4;nt++){
                int col = wn*32 + nt*8 + lr;
                b[nt][0]=Ws[st][kk+lc][col]; b[nt][1]=Ws[st][kk+lc+4][col];
            }
#pragma unroll
            for (int mt=0;mt<4;mt++)
#pragma unroll
                for (int nt=0;nt<4;nt++)
                    mma8(acc[mt][nt], a[mt][0],a[mt][1],a[mt][2],a[mt][3], b[nt][0],b[nt][1]);
        }
        if (nxt) STORES(st^1);
        __syncthreads();
    }
#pragma unroll
    for (int mt=0;mt<4;mt++){
        int r0 = m0 + wm*64 + mt*16 + lr;
#pragma unroll
        for (int nt=0;nt<4;nt++){
            int c0 = n0 + wn*32 + nt*8 + lc*2;
            float b0 = bias[c0], b1 = bias[c0+1];
            if (r0 < M){
                float2 o = make_float2(acc[mt][nt][0]+b0, acc[mt][nt][1]+b1);
                *reinterpret_cast<float2*>(&C[(size_t)r0*Nn + c0]) = o;
            }
            if (r0+8 < M){
                float2 o = make_float2(acc[mt][nt][2]+b0, acc[mt][nt][3]+b1);
                *reinterpret_cast<float2*>(&C[(size_t)(r0+8)*Nn + c0]) = o;
            }
        }
    }
}

__global__ void __launch_bounds__(256) gemm_qkv_kernel(
        const float* __restrict__ x, const float* __restrict__ l,
        const float* __restrict__ wqkv, const float* __restrict__ bqkv,
        const float* __restrict__ wqkv1, const float* __restrict__ bqkv1){
    int s = blockIdx.z;
    gemm_tf32_body<false>(s ? l : x, nullptr, s ? wqkv1 : wqkv, s ? bqkv1 : bqkv,
                          s ? g_qkv1 : g_qkv0, MROWS, QKVN, DIMM);
}

// MLP reads the two attnv partials and sums them on the fly (fp32) before tf32 convert.
__global__ void __launch_bounds__(256) gemm_mlp_kernel(
        const float* __restrict__ w_mlp, const float* __restrict__ b_mlp,
        const float* __restrict__ w_mlp1, const float* __restrict__ b_mlp1,
        float* __restrict__ out){
    int s = blockIdx.z;
    gemm_tf32_body<true>(s ? g_ao1 : g_ao0, s ? g_ap1 : g_ap0,
                         s ? w_mlp1 : w_mlp, s ? b_mlp1 : b_mlp,
                         out + (size_t)s*MROWS*DIMM, MROWS, DIMM, DIMM);
}

// ---------------- dots + dots1 + fused sup + batch max (tf32 MMA) ----------------
// block tile 64(i) x 128(j) per (b,h); 8 warps as 2x4, warp tile 32x32, dual stream
__global__ void __launch_bounds__(256) dots_sup_kernel(
        const float* __restrict__ c1w, const float* __restrict__ c1b,
        const float* __restrict__ bn_g, const float* __restrict__ bn_b,
        const float* __restrict__ bn_m, const float* __restrict__ bn_v,
        const float* __restrict__ c2w, const float* __restrict__ c2b){
    __shared__ unsigned Qs[2][64][20];
    __shared__ unsigned Ks[2][128][20];
    __shared__ float red0[8], red1[8];
    const int tid = threadIdx.x;
    const int lane = tid & 31, wrp = tid >> 5;
    const int wm = wrp >> 2, wn = wrp & 3;
    const int lr = lane >> 2, lc = lane & 3;
    const int bh = blockIdx.z;
    const int b = bh >> 3, h = bh & 7;
    const int i0 = blockIdx.y * 64, j0 = blockIdx.x * 128;

    const float* qp0 = g_qkv0 + (size_t)b*SEQ*QKVN + h*64;
    const float* qp1 = g_qkv1 + (size_t)b*SEQ*QKVN + h*64;
    const float* kp0 = qp0 + DIMM;
    const float* kp1 = qp1 + DIMM;

    float acc[2][2][4][4];
#pragma unroll
    for (int s=0;s<2;s++)
#pragma unroll
        for (int mt=0;mt<2;mt++)
#pragma unroll
            for (int nt=0;nt<4;nt++)
#pragma unroll
                for (int e=0;e<4;e++) acc[s][mt][nt][e]=0.f;

    for (int c0=0;c0<64;c0+=16){
        {   // Q tiles: 64x16 per stream, 1 float4/thread/stream
            int r = tid >> 2, c = (tid & 3) * 4;
            int gi = i0 + r;
            float4 v0 = make_float4(0,0,0,0), v1 = v0;
            if (gi < SEQ){
                v0 = *reinterpret_cast<const float4*>(&qp0[(size_t)gi*QKVN + c0 + c]);
                v1 = *reinterpret_cast<const float4*>(&qp1[(size_t)gi*QKVN + c0 + c]);
            }
            st4tf(&Qs[0][r][c], v0);
            st4tf(&Qs[1][r][c], v1);
        }
#pragma unroll
        for (int t=0;t<2;t++){ // K tiles: 128x16 per stream, 2 float4/thread/stream
            int idx = tid + t*256;
            int r = idx >> 2, c = (idx & 3) * 4;
            int gj = j0 + r;
            float4 v0 = make_float4(0,0,0,0), v1 = v0;
            if (gj < SEQ){
                v0 = *reinterpret_cast<const float4*>(&kp0[(size_t)gj*QKVN + c0 + c]);
                v1 = *reinterpret_cast<const float4*>(&kp1[(size_t)gj*QKVN + c0 + c]);
            }
            st4tf(&Ks[0][r][c], v0);
            st4tf(&Ks[1][r][c], v1);
        }
        __syncthreads();
#pragma unroll
        for (int kk=0;kk<16;kk+=8){
            unsigned a[2][2][4], bb[2][4][2];
#pragma unroll
            for (int s=0;s<2;s++){
#pragma unroll
                for (int mt=0;mt<2;mt++){
                    int row = wm*32 + mt*16 + lr;
                    a[s][mt][0]=Qs[s][row  ][kk+lc];   a[s][mt][1]=Qs[s][row+8][kk+lc];
                    a[s][mt][2]=Qs[s][row  ][kk+lc+4]; a[s][mt][3]=Qs[s][row+8][kk+lc+4];
                }
#pragma unroll
                for (int nt=0;nt<4;nt++){
                    int col = wn*32 + nt*8 + lr;
                    bb[s][nt][0]=Ks[s][col][kk+lc]; bb[s][nt][1]=Ks[s][col][kk+lc+4];
                }
            }
#pragma unroll
            for (int s=0;s<2;s++)
#pragma unroll
                for (int mt=0;mt<2;mt++)
#pragma unroll
                    for (int nt=0;nt<4;nt++)
                        mma8(acc[s][mt][nt], a[s][mt][0],a[s][mt][1],a[s][mt][2],a[s][mt][3],
                             bb[s][nt][0],bb[s][nt][1]);
        }
        __syncthreads();
    }

    // per-head fused conv->BN->leaky->conv coefficients
    float Ao[NAA], Bo[NAA], Co[NAA], Wo[NAA];
#pragma unroll
    for (int o=0;o<NAA;o++){
        int idx = h*NAA + o;
        float inv = rsqrtf(bn_v[idx] + 1e-5f) * bn_g[idx];
        Ao[o] = c1w[idx*2]   * inv;
        Bo[o] = c1w[idx*2+1] * inv;
        Co[o] = (c1b[idx] - bn_m[idx]) * inv + bn_b[idx];
        Wo[o] = c2w[idx];
    }
    float c2bh = c2b[h];

    float lm0 = -INFINITY, lm1 = -INFINITY;
    const size_t rbase = (size_t)bh*SEQ;
#pragma unroll
    for (int mt=0;mt<2;mt++){
#pragma unroll
        for (int half=0;half<2;half++){
            int row = i0 + wm*32 + mt*16 + lr + half*8;
            if (row >= SEQ) continue;
#pragma unroll
            for (int nt=0;nt<4;nt++){
                int c0 = j0 + wn*32 + nt*8 + lc*2;
                // scalar stores — SEQ odd, vector stores would misalign on odd rows
#pragma unroll
                for (int e=0;e<2;e++){
                    int gj = c0 + e;
                    if (gj >= SEQ) continue;
                    float d  = acc[0][mt][nt][half*2+e]*SCALE_F;
                    float d1 = acc[1][mt][nt][half*2+e]*SCALE_F;
                    float sup = c2bh;
#pragma unroll
                    for (int o=0;o<NAA;o++){
                        float t = fmaf(Ao[o], d, fmaf(Bo[o], d1, Co[o]));
                        t = (t > 0.f) ? t : 0.01f*t;
                        sup = fmaf(t, Wo[o], sup);
                    }
                    float fd = d + sup, fd1 = d1 + sup;
                    size_t off = (rbase + row)*SEQ + gj;
                    g_dots0[off] = fd;
                    g_dots1[off] = fd1;
                    lm0 = fmaxf(lm0, fd);
                    lm1 = fmaxf(lm1, fd1);
                }
            }
        }
    }
#pragma unroll
    for (int off=16; off; off>>=1){
        lm0 = fmaxf(lm0, __shfl_xor_sync(0xffffffffu, lm0, off));
        lm1 = fmaxf(lm1, __shfl_xor_sync(0xffffffffu, lm1, off));
    }
    if (lane==0){ red0[wrp]=lm0; red1[wrp]=lm1; }
    __syncthreads();
    if (tid==0){
        float m0v=red0[0], m1v=red1[0];
        for (int w2=1;w2<8;w2++){ m0v=fmaxf(m0v,red0[w2]); m1v=fmaxf(m1v,red1[w2]); }
        atomicMaxFloat(&g_bmax[b],    m0v);
        atomicMaxFloat(&g_bmax[BB+b], m1v);
    }
}

// ---------------- fused row softmax stats + KL partials ----------------
__global__ void __launch_bounds__(256) rowkl_kernel(){
    const int warp = threadIdx.x >> 5;
    const int lane = threadIdx.x & 31;
    const int row = blockIdx.x*8 + warp;          // 0..NROWS-1
    const int b = row / (NH*SEQ);
    const float* p0 = g_dots0 + (size_t)row*SEQ;
    const float* p1 = g_dots1 + (size_t)row*SEQ;

    float v0[19], v1[19];
    float m0 = -INFINITY, m1 = -INFINITY;
#pragma unroll
    for (int t=0;t<19;t++){
        int j = lane + t*32;
        bool ok = (j < SEQ);
        v0[t] = ok ? p0[j] : -INFINITY;
        v1[t] = ok ? p1[j] : -INFINITY;
        m0 = fmaxf(m0, v0[t]);
        m1 = fmaxf(m1, v1[t]);
    }
#pragma unroll
    for (int off=16; off; off>>=1){
        m0 = fmaxf(m0, __shfl_xor_sync(0xffffffffu, m0, off));
        m1 = fmaxf(m1, __shfl_xor_sync(0xffffffffu, m1, off));
    }
    float s0=0.f, s1=0.f, tacc=0.f;
#pragma unroll
    for (int t=0;t<19;t++){
        int j = lane + t*32;
        if (j < SEQ){
            s0 += __expf(v0[t] - m0);
            float e1 = __expf(v1[t] - m1);
            s1 += e1;
            tacc = fmaf(e1, v1[t] - v0[t], tacc);
        }
    }
#pragma unroll
    for (int off=16; off; off>>=1){
        s0 += __shfl_xor_sync(0xffffffffu, s0, off);
        s1 += __shfl_xor_sync(0xffffffffu, s1, off);
        tacc += __shfl_xor_sync(0xffffffffu, tacc, off);
    }
    __shared__ float rz0[8], rz1[8], rS[8];
    if (lane==0){
        g_rmax[row] = m0;         g_rsum[row] = s0;
        g_rmax[NROWS+row] = m1;   g_rsum[NROWS+row] = s1;
        float e0b = __expf(m0 - g_bmax[b]);
        float e1b = __expf(m1 - g_bmax[BB+b]);
        rz0[warp] = s0 * e0b;
        rz1[warp] = s1 * e1b;
        rS[warp]  = tacc * e1b;
    }
    __syncthreads();
    if (threadIdx.x==0){
        float Z0=0,Z1=0,S=0;
#pragma unroll
        for (int w=0;w<8;w++){ Z0+=rz0[w]; Z1+=rz1[w]; S+=rS[w]; }
        int kb = blockIdx.x - b*PPB;
        int o = (b*PPB + kb)*3;
        g_part[o]=Z0; g_part[o+1]=Z1; g_part[o+2]=S;
    }
}

__global__ void loss_kernel(float* __restrict__ out_loss){
    __shared__ float sh[3][256];
    const int t = threadIdx.x;
    float total = 0.f;
    for (int b=0;b<BB;b++){
        float Z0=0,Z1=0,S=0;
        for (int k=t;k<PPB;k+=256){
            int o=(b*PPB+k)*3;
            Z0+=g_part[o]; Z1+=g_part[o+1]; S+=g_part[o+2];
        }
        sh[0][t]=Z0; sh[1][t]=Z1; sh[2][t]=S;
        __syncthreads();
        for (int off=128; off; off>>=1){
            if (t < off){
                sh[0][t]+=sh[0][t+off];
                sh[1][t]+=sh[1][t+off];
                sh[2][t]+=sh[2][t+off];
            }
            __syncthreads();
        }
        if (t==0){
            total += sh[2][0]/sh[1][0]
                   + (g_bmax[b] + logf(sh[0][0]))
                   - (g_bmax[BB+b] + logf(sh[1][0]));
        }
        __syncthreads();
    }
    if (t==0) *out_loss = total * (1.0f/BB);
}

// ---------------- attn @ V, tf32 MMA, split-K over j, fused softmax normalization --------
// grid: (2 halves, 10 row-strips, 64 = s*32+bh). Each half writes its own partial buffer;
// gemm_mlp sums the two partials on load. Deterministic: no atomics.
__global__ void __launch_bounds__(256) attnv_kernel(){
    __shared__ unsigned Es[64][36];
    __shared__ unsigned Vs[32][72];
    __shared__ float rm[64], rs[64];
    const int tid = threadIdx.x;
    const int lane = tid & 31, wrp = tid >> 5;
    const int wm = wrp >> 2, wn = wrp & 3;
    const int lr = lane >> 2, lc = lane & 3;
    const int half = blockIdx.x;           // j-half: 0 -> [0,320), 1 -> [320,577)
    const int z = blockIdx.z;
    const int s = z >> 5, bh = z & 31;
    const int b = bh >> 3, h = bh & 7;
    const int i0 = blockIdx.y * 64;
    const float* dots = (s ? g_dots1 : g_dots0) + (size_t)bh*NN2;
    const float* vptr = (s ? g_qkv1 : g_qkv0) + (size_t)b*SEQ*QKVN + 2*DIMM + h*64;
    float* ao;
    if (half==0) ao = (s ? g_ao1 : g_ao0) + (size_t)b*SEQ*DIMM + h*64;
    else         ao = (s ? g_ap1 : g_ap0) + (size_t)b*SEQ*DIMM + h*64;

    if (tid < 64){
        int gi = i0 + tid;
        int ri = s*NROWS + bh*SEQ + gi;
        rm[tid] = (gi<SEQ) ? g_rmax[ri] : 0.f;
        rs[tid] = (gi<SEQ) ? g_rsum[ri] : 1.f;
    }
    __syncthreads();

    float acc[2][2][4];
#pragma unroll
    for (int mt=0;mt<2;mt++)
#pragma unroll
        for (int nt=0;nt<2;nt++)
#pragma unroll
            for (int e=0;e<4;e++) acc[mt][nt][e]=0.f;

    const int jbeg = half * 320;
    const int jend = half ? SEQ : 320;
    for (int j0=jbeg; j0<jend; j0+=32){
#pragma unroll
        for (int t=0;t<8;t++){   // Es: 64x32 exps, 8/thread
            int idx = tid + t*256;
            int i = idx >> 5, j = idx & 31;
            int gi = i0+i, gj = j0+j;
            float w = 0.f;
            if (gi < SEQ && gj < SEQ) w = __expf(dots[(size_t)gi*SEQ+gj] - rm[i]);
            Es[i][j] = f2tf(w);
        }
#pragma unroll
        for (int t=0;t<2;t++){   // Vs: 32x64, 2 float4/thread
            int idx = tid + t*256;
            int j = idx >> 4, c = (idx & 15)*4;
            int gj = j0 + j;
            float4 v = make_float4(0,0,0,0);
            if (gj < SEQ) v = *reinterpret_cast<const float4*>(&vptr[(size_t)gj*QKVN + c]);
            st4tf(&Vs[j][c], v);
        }
        __syncthreads();
#pragma unroll
        for (int kk=0;kk<32;kk+=8){
            unsigned a[2][4], bf[2][2];
#pragma unroll
            for (int mt=0;mt<2;mt++){
                int row = wm*32 + mt*16 + lr;
                a[mt][0]=Es[row  ][kk+lc];   a[mt][1]=Es[row+8][kk+lc];
                a[mt][2]=Es[row  ][kk+lc+4]; a[mt][3]=Es[row+8][kk+lc+4];
            }
#pragma unroll
            for (int nt=0;nt<2;nt++){
                int col = wn*16 + nt*8 + lr;
                bf[nt][0]=Vs[kk+lc][col]; bf[nt][1]=Vs[kk+lc+4][col];
            }
#pragma unroll
            for (int mt=0;mt<2;mt++)
#pragma unroll
                for (int nt=0;nt<2;nt++)
                    mma8(acc[mt][nt], a[mt][0],a[mt][1],a[mt][2],a[mt][3], bf[nt][0],bf[nt][1]);
        }
        __syncthreads();
    }
#pragma unroll
    for (int mt=0;mt<2;mt++){
        int lrow = wm*32 + mt*16 + lr;
        int r0 = i0 + lrow;
#pragma unroll
        for (int nt=0;nt<2;nt++){
            int c0 = wn*16 + nt*8 + lc*2;
            if (r0 < SEQ){
                float inv = 1.f / rs[lrow];
                float2 o = make_float2(acc[mt][nt][0]*inv, acc[mt][nt][1]*inv);
                *reinterpret_cast<float2*>(&ao[(size_t)r0*DIMM + c0]) = o;
            }
            if (r0+8 < SEQ){
                float inv = 1.f / rs[lrow+8];
                float2 o = make_float2(acc[mt][nt][2]*inv, acc[mt][nt][3]*inv);
                *reinterpret_cast<float2*>(&ao[(size_t)(r0+8)*DIMM + c0]) = o;
            }
        }
    }
}

// ---------------- host launcher ----------------
extern "C" void kernel_launch(void* const* d_in, const int* in_sizes, int n_in,
                              void* d_out, int out_size){
    (void)in_sizes; (void)n_in; (void)out_size;
    const float* x     = (const float*)d_in[0];
    const float* l     = (const float*)d_in[1];
    /* d_in[2] = mask: unused by the module */
    const float* wqkv  = (const float*)d_in[3];
    const float* bqkv  = (const float*)d_in[4];
    const float* wqkv1 = (const float*)d_in[5];
    const float* bqkv1 = (const float*)d_in[6];
    const float* w_mlp  = (const float*)d_in[7];
    const float* b_mlp  = (const float*)d_in[8];
    const float* w_mlp1 = (const float*)d_in[9];
    const float* b_mlp1 = (const float*)d_in[10];
    const float* c1w  = (const float*)d_in[11];
    const float* c1b  = (const float*)d_in[12];
    const float* bn_g = (const float*)d_in[13];
    const float* bn_b = (const float*)d_in[14];
    const float* bn_m = (const float*)d_in[15];
    const float* bn_v = (const float*)d_in[16];
    const float* c2w  = (const float*)d_in[17];
    const float* c2b  = (const float*)d_in[18];
    float* out = (float*)d_out;

    init_kernel<<<1, 32>>>();
    gemm_qkv_kernel<<<dim3(QKVN/128, (MROWS+127)/128, 2), 256>>>(x, l, wqkv, bqkv, wqkv1, bqkv1);
    dots_sup_kernel<<<dim3(5, 10, BB*NH), 256>>>(c1w, c1b, bn_g, bn_b, bn_m, bn_v, c2w, c2b);
    rowkl_kernel<<<NROWS/8, 256>>>();
    loss_kernel<<<1, 256>>>(out + 2*(size_t)MROWS*DIMM);
    attnv_kernel<<<dim3(2, 10, 64), 256>>>();
    gemm_mlp_kernel<<<dim3(DIMM/128, (MROWS+127)/128, 2), 256>>>(w_mlp, b_mlp, w_mlp1, b_mlp1, out);
}